// round 1
// baseline (speedup 1.0000x reference)
#include <cuda_runtime.h>
#include <math_constants.h>

// ---------------------------------------------------------------------------
// MaxIntersection: winding-number interior masks + pairwise distance stats.
//   inputs:  v1 [B,N,3] f32, v2 [B,N,3] f32, faces [NF,3] i32   (B=2)
//   output:  [5,B] f32 = {min_dist, max_12, mean_12, max_21, mean_21}
// dir 0: points=v1, tris from v2, row_min (v1 -> nearest v2)
// dir 1: points=v2, tris from v1, col_min (v2 -> nearest v1)
// ---------------------------------------------------------------------------

#define BATCH   2
#define NMAX    8192
#define NFMAX   4096
#define FTILE   500
#define FCMAX   ((NFMAX + FTILE - 1) / FTILE)   // 9
#define OCH     4
#define PTILE   256

// scratch (static device memory; no allocation allowed)
__device__ float g_tris [2 * BATCH * NFMAX * 12];          // [dir][b][f][3 verts x float4]
__device__ float g_omega[2 * BATCH * FCMAX * NMAX];        // partial atan2 sums
__device__ int   g_mask [2 * BATCH * NMAX];
__device__ int   g_rminsq[2 * BATCH * NMAX];               // float bits of min squared dist

// --------------------------- kernel A: gather triangle soup ----------------
__global__ void build_tris_kernel(const float* __restrict__ v1,
                                  const float* __restrict__ v2,
                                  const int* __restrict__ faces,
                                  int N, int NF) {
    int idx = blockIdx.x * blockDim.x + threadIdx.x;   // over 2*B*NF*3 vertices
    int total = 2 * BATCH * NF * 3;
    if (idx >= total) return;
    int k   = idx % 3;
    int f   = (idx / 3) % NF;
    int b   = (idx / (3 * NF)) % BATCH;
    int dir = idx / (3 * NF * BATCH);
    const float* src = (dir == 0) ? v2 : v1;           // dir0 tris from v2, dir1 from v1
    int vi = faces[f * 3 + k];
    const float* p = src + ((size_t)b * N + vi) * 3;
    float* dst = g_tris + (((size_t)(dir * BATCH + b) * NF + f) * 3 + k) * 4;
    dst[0] = p[0]; dst[1] = p[1]; dst[2] = p[2]; dst[3] = 0.f;
}

// --------------------------- kernel B: winding partial sums ----------------
__global__ void winding_kernel(const float* __restrict__ v1,
                               const float* __restrict__ v2,
                               int N, int NF, int FCH) {
    int dir = blockIdx.z / FCH;
    int fc  = blockIdx.z % FCH;
    int b   = blockIdx.y;
    int i   = blockIdx.x * blockDim.x + threadIdx.x;

    __shared__ float4 s_tri[FTILE * 3];

    int f0 = fc * FTILE;
    int nf = min(FTILE, NF - f0);
    const float4* gsrc =
        (const float4*)(g_tris + ((size_t)(dir * BATCH + b) * NF + f0) * 12);
    for (int t = threadIdx.x; t < nf * 3; t += blockDim.x) s_tri[t] = gsrc[t];
    __syncthreads();

    if (i >= N) return;

    const float* pts = (dir == 0) ? v1 : v2;
    const float* p = pts + ((size_t)b * N + i) * 3;
    float px = p[0], py = p[1], pz = p[2];

    float acc = 0.f;
    #pragma unroll 2
    for (int f = 0; f < nf; ++f) {
        float4 A  = s_tri[f * 3 + 0];
        float4 Bv = s_tri[f * 3 + 1];
        float4 C  = s_tri[f * 3 + 2];
        float ax = A.x - px,  ay = A.y - py,  az = A.z - pz;
        float bx = Bv.x - px, by = Bv.y - py, bz = Bv.z - pz;
        float cx = C.x - px,  cy = C.y - py,  cz = C.z - pz;
        // det = a . (b x c)
        float ux = by * cz - bz * cy;
        float uy = bz * cx - bx * cz;
        float uz = bx * cy - by * cx;
        float det = ax * ux + ay * uy + az * uz;
        float la = sqrtf(ax * ax + ay * ay + az * az);
        float lb = sqrtf(bx * bx + by * by + bz * bz);
        float lc = sqrtf(cx * cx + cy * cy + cz * cz);
        float dab = ax * bx + ay * by + az * bz;
        float dbc = bx * cx + by * cy + bz * cz;
        float dca = cx * ax + cy * ay + cz * az;
        float denom = la * lb * lc + dab * lc + dbc * la + dca * lb;
        acc += atan2f(det, denom);   // omega/2; factor 2 folded into normalization
    }
    g_omega[((size_t)(dir * BATCH + b) * FCMAX + fc) * NMAX + i] = acc;
}

// --------------------------- kernel C: reduce chunks -> mask, init rmin ----
__global__ void mask_kernel(int N, int FCH) {
    int i   = blockIdx.x * blockDim.x + threadIdx.x;
    int b   = blockIdx.y;
    int dir = blockIdx.z;
    if (i >= N) return;
    float s = 0.f;
    for (int fc = 0; fc < FCH; ++fc)
        s += g_omega[((size_t)(dir * BATCH + b) * FCMAX + fc) * NMAX + i];
    // w = (2 * sum_atan2) / (4*pi) = sum / (2*pi)
    float w = s * 0.15915494309189535f;
    int slot = (dir * BATCH + b) * NMAX + i;
    g_mask[slot]   = (w >= 0.99f) ? 1 : 0;
    g_rminsq[slot] = 0x7F7FFFFF;   // FLT_MAX bits
}

// --------------------------- kernel E: pairwise min (squared) --------------
__global__ void pairmin_kernel(const float* __restrict__ v1,
                               const float* __restrict__ v2,
                               int N) {
    int dir = blockIdx.z / OCH;
    int oc  = blockIdx.z % OCH;
    int b   = blockIdx.y;
    int i   = blockIdx.x * blockDim.x + threadIdx.x;

    const float* Q = (dir == 0) ? v1 : v2;
    const float* O = (dir == 0) ? v2 : v1;

    __shared__ float4 s_o[PTILE];

    float qx = 0.f, qy = 0.f, qz = 0.f, q2 = 0.f;
    bool valid = (i < N);
    if (valid) {
        const float* q = Q + ((size_t)b * N + i) * 3;
        qx = q[0]; qy = q[1]; qz = q[2];
        qx = qx; q2 = qx * qx + qy * qy + qz * qz;
    }

    int per = (N + OCH - 1) / OCH;
    int j0 = oc * per;
    int j1 = min(N, j0 + per);

    float m = CUDART_INF_F;
    for (int t0 = j0; t0 < j1; t0 += PTILE) {
        int cnt = min(PTILE, j1 - t0);
        __syncthreads();
        if ((int)threadIdx.x < cnt) {
            const float* o = O + ((size_t)b * N + t0 + threadIdx.x) * 3;
            float ox = o[0], oy = o[1], oz = o[2];
            s_o[threadIdx.x] = make_float4(ox, oy, oz, ox * ox + oy * oy + oz * oz);
        }
        __syncthreads();
        if (valid) {
            #pragma unroll 4
            for (int j = 0; j < cnt; ++j) {
                float4 o = s_o[j];
                float dot = qx * o.x + qy * o.y + qz * o.z;
                float d2 = fmaf(-2.f, dot, q2 + o.w);   // reference formula
                d2 = fmaxf(d2, 0.f);
                m = fminf(m, d2);
            }
        }
    }
    if (valid)
        atomicMin(&g_rminsq[(dir * BATCH + b) * NMAX + i], __float_as_int(m));
}

// --------------------------- kernel F: masked stats + output ---------------
__global__ void stats_kernel(float* __restrict__ out, int N) {
    int b   = blockIdx.x;
    int dir = blockIdx.y;
    int t   = threadIdx.x;

    __shared__ float smax[256], ssum[256], smin[256];
    __shared__ int   scnt[256];

    float mx = -CUDART_INF_F, sum = 0.f, mnsq = CUDART_INF_F;
    int cnt = 0;
    int base = (dir * BATCH + b) * NMAX;
    for (int i = t; i < N; i += 256) {
        float rsq = __int_as_float(g_rminsq[base + i]);
        float r = sqrtf(rsq);
        if (g_mask[base + i]) { mx = fmaxf(mx, r); sum += r; cnt++; }
        mnsq = fminf(mnsq, rsq);
    }
    smax[t] = mx; ssum[t] = sum; smin[t] = mnsq; scnt[t] = cnt;
    __syncthreads();
    for (int s = 128; s > 0; s >>= 1) {
        if (t < s) {
            smax[t] = fmaxf(smax[t], smax[t + s]);
            ssum[t] += ssum[t + s];
            smin[t] = fminf(smin[t], smin[t + s]);
            scnt[t] += scnt[t + s];
        }
        __syncthreads();
    }
    if (t == 0) {
        int   c   = scnt[0];
        float mxv = (c > 0) ? smax[0] : 0.f;
        float mnv = (c > 0) ? ssum[0] / (float)c : 0.f;
        out[(1 + 2 * dir) * BATCH + b] = mxv;   // max_12 / max_21
        out[(2 + 2 * dir) * BATCH + b] = mnv;   // mean_12 / mean_21
        if (dir == 0) out[b] = sqrtf(smin[0]);  // min_dist
    }
}

// ---------------------------------------------------------------------------
extern "C" void kernel_launch(void* const* d_in, const int* in_sizes, int n_in,
                              void* d_out, int out_size) {
    const float* v1    = (const float*)d_in[0];
    const float* v2    = (const float*)d_in[1];
    const int*   faces = (const int*)d_in[2];
    float* out = (float*)d_out;

    int N  = in_sizes[0] / (BATCH * 3);
    int NF = in_sizes[2] / 3;
    int FCH = (NF + FTILE - 1) / FTILE;
    int pchunks = (N + 255) / 256;

    // A: gather triangle soups
    {
        int total = 2 * BATCH * NF * 3;
        build_tris_kernel<<<(total + 255) / 256, 256>>>(v1, v2, faces, N, NF);
    }
    // B: winding partial sums
    {
        dim3 grid(pchunks, BATCH, 2 * FCH);
        winding_kernel<<<grid, 256>>>(v1, v2, N, NF, FCH);
    }
    // C: masks + rmin init
    {
        dim3 grid(pchunks, BATCH, 2);
        mask_kernel<<<grid, 256>>>(N, FCH);
    }
    // E: pairwise mins
    {
        dim3 grid(pchunks, BATCH, 2 * OCH);
        pairmin_kernel<<<grid, PTILE>>>(v1, v2, N);
    }
    // F: stats
    {
        dim3 grid(BATCH, 2);
        stats_kernel<<<grid, 256>>>(out, N);
    }
}

// round 3
// speedup vs baseline: 1.4130x; 1.4130x over previous
#include <cuda_runtime.h>
#include <math_constants.h>

// ---------------------------------------------------------------------------
// MaxIntersection: winding-number interior masks + pairwise distance stats.
//   inputs:  v1 [B,N,3] f32, v2 [B,N,3] f32, faces [NF,3] i32   (B=2)
//   output:  [5,B] f32 = {min_dist, max_12, mean_12, max_21, mean_21}
// dir 0: points=v1, tris from v2, row_min (v1 -> nearest v2)
// dir 1: points=v2, tris from v1, col_min (v2 -> nearest v1)
// ---------------------------------------------------------------------------

#define BATCH   2
#define NMAX    8192
#define NFMAX   4096
#define FTILE   500
#define FCMAX   ((NFMAX + FTILE - 1) / FTILE)   // 9
#define OCH     6
#define PTILE   128
#define IPT     4

// scratch (static device memory; no allocation allowed)
__device__ float g_tris [2 * BATCH * NFMAX * 12];          // [dir][b][f][3 verts x float4]
__device__ float g_omega[2 * BATCH * FCMAX * NMAX];        // partial atan2 sums
__device__ int   g_mask [2 * BATCH * NMAX];
__device__ int   g_rminsq[2 * BATCH * NMAX];               // float bits of min sq dist

// --------------------------- fast math helpers -----------------------------
__device__ __forceinline__ float rsqrt_ap(float x) {
    float r; asm("rsqrt.approx.f32 %0, %1;" : "=f"(r) : "f"(x)); return r;
}
__device__ __forceinline__ float rcp_ap(float x) {
    float r; asm("rcp.approx.f32 %0, %1;" : "=f"(r) : "f"(x)); return r;
}

// max error ~3e-7 rad; full-quadrant atan2
__device__ __forceinline__ float fast_atan2f(float y, float x) {
    float ax = fabsf(x), ay = fabsf(y);
    float mx = fmaxf(ax, ay);
    float mn = fminf(ax, ay);
    float t  = mn * rcp_ap(fmaxf(mx, 1e-37f));   // [0,1]
    float s  = t * t;
    float p  =              -0.0117212f;
    p = fmaf(p, s,  0.05265332f);
    p = fmaf(p, s, -0.11643287f);
    p = fmaf(p, s,  0.19354346f);
    p = fmaf(p, s, -0.33262347f);
    p = fmaf(p, s,  0.99997726f);
    float r = p * t;
    r = (ay > ax)  ? (1.5707963267948966f - r) : r;
    r = (x < 0.f)  ? (3.1415926535897932f - r) : r;
    return copysignf(r, y);
}

// --------------------------- kernel A: gather triangle soup ----------------
__global__ void build_tris_kernel(const float* __restrict__ v1,
                                  const float* __restrict__ v2,
                                  const int* __restrict__ faces,
                                  int N, int NF) {
    int idx = blockIdx.x * blockDim.x + threadIdx.x;   // over 2*B*NF*3 vertices
    int total = 2 * BATCH * NF * 3;
    if (idx >= total) return;
    int k   = idx % 3;
    int f   = (idx / 3) % NF;
    int b   = (idx / (3 * NF)) % BATCH;
    int dir = idx / (3 * NF * BATCH);
    const float* src = (dir == 0) ? v2 : v1;           // dir0 tris from v2, dir1 from v1
    int vi = faces[f * 3 + k];
    const float* p = src + ((size_t)b * N + vi) * 3;
    float* dst = g_tris + (((size_t)(dir * BATCH + b) * NF + f) * 3 + k) * 4;
    dst[0] = p[0]; dst[1] = p[1]; dst[2] = p[2]; dst[3] = 0.f;
}

// --------------------------- kernel B: winding partial sums ----------------
__global__ void __launch_bounds__(256) winding_kernel(const float* __restrict__ v1,
                               const float* __restrict__ v2,
                               int N, int NF, int FCH) {
    int dir = blockIdx.z / FCH;
    int fc  = blockIdx.z % FCH;
    int b   = blockIdx.y;
    int i   = blockIdx.x * blockDim.x + threadIdx.x;

    __shared__ float4 s_tri[FTILE * 3];

    int f0 = fc * FTILE;
    int nf = min(FTILE, NF - f0);
    const float4* gsrc =
        (const float4*)(g_tris + ((size_t)(dir * BATCH + b) * NF + f0) * 12);
    for (int t = threadIdx.x; t < nf * 3; t += blockDim.x) s_tri[t] = gsrc[t];
    __syncthreads();

    if (i >= N) return;

    const float* pts = (dir == 0) ? v1 : v2;
    const float* p = pts + ((size_t)b * N + i) * 3;
    float px = p[0], py = p[1], pz = p[2];

    float acc = 0.f;
    #pragma unroll 2
    for (int f = 0; f < nf; ++f) {
        float4 A  = s_tri[f * 3 + 0];
        float4 Bv = s_tri[f * 3 + 1];
        float4 C  = s_tri[f * 3 + 2];
        float ax = A.x - px,  ay = A.y - py,  az = A.z - pz;
        float bx = Bv.x - px, by = Bv.y - py, bz = Bv.z - pz;
        float cx = C.x - px,  cy = C.y - py,  cz = C.z - pz;
        // det = a . (b x c)
        float ux = by * cz - bz * cy;
        float uy = bz * cx - bx * cz;
        float uz = bx * cy - by * cx;
        float det = ax * ux + ay * uy + az * uz;
        float r2a = ax * ax + ay * ay + az * az;
        float r2b = bx * bx + by * by + bz * bz;
        float r2c = cx * cx + cy * cy + cz * cz;
        float la = r2a * rsqrt_ap(fmaxf(r2a, 1e-30f));
        float lb = r2b * rsqrt_ap(fmaxf(r2b, 1e-30f));
        float lc = r2c * rsqrt_ap(fmaxf(r2c, 1e-30f));
        float dab = ax * bx + ay * by + az * bz;
        float dbc = bx * cx + by * cy + bz * cz;
        float dca = cx * ax + cy * ay + cz * az;
        // denom = la*lb*lc + dab*lc + dbc*la + dca*lb
        float denom = fmaf(fmaf(la, lb, dab), lc, fmaf(dbc, la, dca * lb));
        acc += fast_atan2f(det, denom);   // omega/2; factor 2 folded into norm
    }
    g_omega[((size_t)(dir * BATCH + b) * FCMAX + fc) * NMAX + i] = acc;
}

// --------------------------- kernel C: reduce chunks -> mask, init rmin ----
__global__ void mask_kernel(int N, int FCH) {
    int i   = blockIdx.x * blockDim.x + threadIdx.x;
    int b   = blockIdx.y;
    int dir = blockIdx.z;
    if (i >= N) return;
    float s = 0.f;
    for (int fc = 0; fc < FCH; ++fc)
        s += g_omega[((size_t)(dir * BATCH + b) * FCMAX + fc) * NMAX + i];
    // w = (2 * sum_atan2) / (4*pi) = sum / (2*pi)
    float w = s * 0.15915494309189535f;
    int slot = (dir * BATCH + b) * NMAX + i;
    g_mask[slot]   = (w >= 0.99f) ? 1 : 0;
    g_rminsq[slot] = 0x7F7FFFFF;   // FLT_MAX bits
}

// --------------------------- kernel E: pairwise min (squared) --------------
// Each thread handles IPT=4 query points (strided by PTILE within the block's
// span) against a column chunk of the other cloud staged in smem.
__global__ void __launch_bounds__(PTILE) pairmin_kernel(const float* __restrict__ v1,
                               const float* __restrict__ v2,
                               int N) {
    int dir = blockIdx.z / OCH;
    int oc  = blockIdx.z % OCH;
    int b   = blockIdx.y;
    int i0  = blockIdx.x * (PTILE * IPT) + threadIdx.x;

    const float* Q = (dir == 0) ? v1 : v2;
    const float* O = (dir == 0) ? v2 : v1;

    __shared__ float4 s_o[PTILE];

    float qx[IPT], qy[IPT], qz[IPT], q2[IPT];
    bool  vld[IPT];
    #pragma unroll
    for (int p = 0; p < IPT; ++p) {
        int i = i0 + p * PTILE;
        vld[p] = (i < N);
        float x = 0.f, y = 0.f, z = 0.f;
        if (vld[p]) {
            const float* q = Q + ((size_t)b * N + i) * 3;
            x = q[0]; y = q[1]; z = q[2];
        }
        qx[p] = x; qy[p] = y; qz[p] = z;
        q2[p] = x * x + y * y + z * z;
    }

    int per = (N + OCH - 1) / OCH;
    int j0 = oc * per;
    int j1 = min(N, j0 + per);

    float m[IPT];
    #pragma unroll
    for (int p = 0; p < IPT; ++p) m[p] = CUDART_INF_F;

    for (int t0 = j0; t0 < j1; t0 += PTILE) {
        int cnt = min(PTILE, j1 - t0);
        __syncthreads();
        if ((int)threadIdx.x < cnt) {
            const float* o = O + ((size_t)b * N + t0 + threadIdx.x) * 3;
            float ox = o[0], oy = o[1], oz = o[2];
            s_o[threadIdx.x] = make_float4(ox, oy, oz, ox * ox + oy * oy + oz * oz);
        }
        __syncthreads();
        #pragma unroll 2
        for (int j = 0; j < cnt; ++j) {
            float4 o = s_o[j];
            #pragma unroll
            for (int p = 0; p < IPT; ++p) {
                float dot = qx[p] * o.x + qy[p] * o.y + qz[p] * o.z;
                // track (o2 - 2 dot); add q2 and clamp at the end (monotone)
                float v = fmaf(-2.f, dot, o.w);
                m[p] = fminf(m[p], v);
            }
        }
    }
    #pragma unroll
    for (int p = 0; p < IPT; ++p) {
        if (vld[p]) {
            float d2 = fmaxf(m[p] + q2[p], 0.f);   // matches ref clamp semantics
            atomicMin(&g_rminsq[(dir * BATCH + b) * NMAX + i0 + p * PTILE],
                      __float_as_int(d2));
        }
    }
}

// --------------------------- kernel F: masked stats + output ---------------
__global__ void stats_kernel(float* __restrict__ out, int N) {
    int b   = blockIdx.x;
    int dir = blockIdx.y;
    int t   = threadIdx.x;

    __shared__ float smax[256], ssum[256], smin[256];
    __shared__ int   scnt[256];

    float mx = -CUDART_INF_F, sum = 0.f, mnsq = CUDART_INF_F;
    int cnt = 0;
    int base = (dir * BATCH + b) * NMAX;
    for (int i = t; i < N; i += 256) {
        float rsq = __int_as_float(g_rminsq[base + i]);
        float r = sqrtf(rsq);
        if (g_mask[base + i]) { mx = fmaxf(mx, r); sum += r; cnt++; }
        mnsq = fminf(mnsq, rsq);
    }
    smax[t] = mx; ssum[t] = sum; smin[t] = mnsq; scnt[t] = cnt;
    __syncthreads();
    for (int s = 128; s > 0; s >>= 1) {
        if (t < s) {
            smax[t] = fmaxf(smax[t], smax[t + s]);
            ssum[t] += ssum[t + s];
            smin[t] = fminf(smin[t], smin[t + s]);
            scnt[t] += scnt[t + s];
        }
        __syncthreads();
    }
    if (t == 0) {
        int   c   = scnt[0];
        float mxv = (c > 0) ? smax[0] : 0.f;
        float mnv = (c > 0) ? ssum[0] / (float)c : 0.f;
        out[(1 + 2 * dir) * BATCH + b] = mxv;   // max_12 / max_21
        out[(2 + 2 * dir) * BATCH + b] = mnv;   // mean_12 / mean_21
        if (dir == 0) out[b] = sqrtf(smin[0]);  // min_dist
    }
}

// ---------------------------------------------------------------------------
extern "C" void kernel_launch(void* const* d_in, const int* in_sizes, int n_in,
                              void* d_out, int out_size) {
    const float* v1    = (const float*)d_in[0];
    const float* v2    = (const float*)d_in[1];
    const int*   faces = (const int*)d_in[2];
    float* out = (float*)d_out;

    int N  = in_sizes[0] / (BATCH * 3);
    int NF = in_sizes[2] / 3;
    int FCH = (NF + FTILE - 1) / FTILE;
    int pchunks = (N + 255) / 256;

    // A: gather triangle soups
    {
        int total = 2 * BATCH * NF * 3;
        build_tris_kernel<<<(total + 255) / 256, 256>>>(v1, v2, faces, N, NF);
    }
    // B: winding partial sums
    {
        dim3 grid(pchunks, BATCH, 2 * FCH);
        winding_kernel<<<grid, 256>>>(v1, v2, N, NF, FCH);
    }
    // C: masks + rmin init
    {
        dim3 grid(pchunks, BATCH, 2);
        mask_kernel<<<grid, 256>>>(N, FCH);
    }
    // E: pairwise mins
    {
        int span = PTILE * IPT;
        dim3 grid((N + span - 1) / span, BATCH, 2 * OCH);
        pairmin_kernel<<<grid, PTILE>>>(v1, v2, N);
    }
    // F: stats
    {
        dim3 grid(BATCH, 2);
        stats_kernel<<<grid, 256>>>(out, N);
    }
}

// round 4
// speedup vs baseline: 1.4370x; 1.0169x over previous
#include <cuda_runtime.h>
#include <math_constants.h>

// ---------------------------------------------------------------------------
// MaxIntersection: winding-number interior masks + pairwise distance stats.
//   inputs:  v1 [B,N,3] f32, v2 [B,N,3] f32, faces [NF,3] i32   (B=2)
//   output:  [5,B] f32 = {min_dist, max_12, mean_12, max_21, mean_21}
// dir 0: points=v1, tris from v2, row_min (v1 -> nearest v2)
// dir 1: points=v2, tris from v1, col_min (v2 -> nearest v1)
// R4: packed f32x2 math (FFMA2) in both hot kernels.
// ---------------------------------------------------------------------------

#define BATCH   2
#define NMAX    8192
#define NFMAX   4096
#define FTILE   500
#define FCMAX   ((NFMAX + FTILE - 1) / FTILE)   // 9
#define OCH     12
#define PTILE   128
#define PT2     128
#define QPK     4        // packed query-pairs per thread (=8 queries)

typedef unsigned long long u64;

// scratch (static device memory; no allocation allowed)
__device__ float g_tris [2 * BATCH * NFMAX * 12];          // [dir][b][f][3 verts x float4]
__device__ float g_omega[2 * BATCH * FCMAX * NMAX];        // partial atan2 sums
__device__ int   g_mask [2 * BATCH * NMAX];
__device__ int   g_rminsq[2 * BATCH * NMAX];               // float bits of min sq dist

// --------------------------- fast math helpers -----------------------------
__device__ __forceinline__ float rsqrt_ap(float x) {
    float r; asm("rsqrt.approx.f32 %0, %1;" : "=f"(r) : "f"(x)); return r;
}
__device__ __forceinline__ float rcp_ap(float x) {
    float r; asm("rcp.approx.f32 %0, %1;" : "=f"(r) : "f"(x)); return r;
}

// --------------------------- packed f32x2 helpers --------------------------
__device__ __forceinline__ u64 pk2(float lo, float hi) {
    u64 r; asm("mov.b64 %0, {%1,%2};" : "=l"(r) : "f"(lo), "f"(hi)); return r;
}
__device__ __forceinline__ void unpk2(u64 v, float& lo, float& hi) {
    asm("mov.b64 {%0,%1}, %2;" : "=f"(lo), "=f"(hi) : "l"(v));
}
__device__ __forceinline__ u64 bc2(float x) { return pk2(x, x); }
__device__ __forceinline__ u64 addpk(u64 a, u64 b) {
    u64 r; asm("add.rn.f32x2 %0, %1, %2;" : "=l"(r) : "l"(a), "l"(b)); return r;
}
__device__ __forceinline__ u64 mulpk(u64 a, u64 b) {
    u64 r; asm("mul.rn.f32x2 %0, %1, %2;" : "=l"(r) : "l"(a), "l"(b)); return r;
}
__device__ __forceinline__ u64 fmapk(u64 a, u64 b, u64 c) {
    u64 r; asm("fma.rn.f32x2 %0, %1, %2, %3;" : "=l"(r) : "l"(a), "l"(b), "l"(c)); return r;
}
__device__ __forceinline__ u64 negpk(u64 a) { return a ^ 0x8000000080000000ULL; }

// --------------------------- kernel A: gather triangle soup ----------------
__global__ void build_tris_kernel(const float* __restrict__ v1,
                                  const float* __restrict__ v2,
                                  const int* __restrict__ faces,
                                  int N, int NF) {
    int idx = blockIdx.x * blockDim.x + threadIdx.x;   // over 2*B*NF*3 vertices
    int total = 2 * BATCH * NF * 3;
    if (idx >= total) return;
    int k   = idx % 3;
    int f   = (idx / 3) % NF;
    int b   = (idx / (3 * NF)) % BATCH;
    int dir = idx / (3 * NF * BATCH);
    const float* src = (dir == 0) ? v2 : v1;           // dir0 tris from v2, dir1 from v1
    int vi = faces[f * 3 + k];
    const float* p = src + ((size_t)b * N + vi) * 3;
    float* dst = g_tris + (((size_t)(dir * BATCH + b) * NF + f) * 3 + k) * 4;
    dst[0] = p[0]; dst[1] = p[1]; dst[2] = p[2]; dst[3] = 0.f;
}

// --------------------------- kernel B: winding partial sums (packed) -------
// 128 threads, each handles 2 points (i0, i0+128); all tri math packed f32x2.
__global__ void __launch_bounds__(128) winding_kernel(const float* __restrict__ v1,
                               const float* __restrict__ v2,
                               int N, int NF, int FCH) {
    int dir = blockIdx.z / FCH;
    int fc  = blockIdx.z % FCH;
    int b   = blockIdx.y;
    int tid = threadIdx.x;
    int i0  = blockIdx.x * 256 + tid;
    int i1  = i0 + 128;

    __shared__ float4 s_tri[FTILE * 3];

    int f0 = fc * FTILE;
    int nf = min(FTILE, NF - f0);
    const float4* gsrc =
        (const float4*)(g_tris + ((size_t)(dir * BATCH + b) * NF + f0) * 12);
    for (int t = tid; t < nf * 3; t += 128) s_tri[t] = gsrc[t];
    __syncthreads();

    if (i0 >= N) return;

    const float* pts = (dir == 0) ? v1 : v2;
    int il1 = min(i1, N - 1);
    const float* p0 = pts + ((size_t)b * N + i0) * 3;
    const float* p1 = pts + ((size_t)b * N + il1) * 3;
    // pre-negated packed point coords (sub -> add)
    u64 nx = pk2(-p0[0], -p1[0]);
    u64 ny = pk2(-p0[1], -p1[1]);
    u64 nz = pk2(-p0[2], -p1[2]);

    const u64 PC0 = bc2(-0.0117212f);
    const u64 PC1 = bc2( 0.05265332f);
    const u64 PC2 = bc2(-0.11643287f);
    const u64 PC3 = bc2( 0.19354346f);
    const u64 PC4 = bc2(-0.33262347f);
    const u64 PC5 = bc2( 0.99997726f);

    float acc0 = 0.f, acc1 = 0.f;
    #pragma unroll 1
    for (int f = 0; f < nf; ++f) {
        float4 A  = s_tri[f * 3 + 0];
        float4 Bv = s_tri[f * 3 + 1];
        float4 C  = s_tri[f * 3 + 2];
        u64 ax = addpk(bc2(A.x),  nx), ay = addpk(bc2(A.y),  ny), az = addpk(bc2(A.z),  nz);
        u64 bx = addpk(bc2(Bv.x), nx), by = addpk(bc2(Bv.y), ny), bz = addpk(bc2(Bv.z), nz);
        u64 cx = addpk(bc2(C.x),  nx), cy = addpk(bc2(C.y),  ny), cz = addpk(bc2(C.z),  nz);
        // u = b x c
        u64 ux = fmapk(by, cz, negpk(mulpk(bz, cy)));
        u64 uy = fmapk(bz, cx, negpk(mulpk(bx, cz)));
        u64 uz = fmapk(bx, cy, negpk(mulpk(by, cx)));
        u64 det = fmapk(az, uz, fmapk(ay, uy, mulpk(ax, ux)));
        u64 r2a = fmapk(az, az, fmapk(ay, ay, mulpk(ax, ax)));
        u64 r2b = fmapk(bz, bz, fmapk(by, by, mulpk(bx, bx)));
        u64 r2c = fmapk(cz, cz, fmapk(cy, cy, mulpk(cx, cx)));
        float h0, h1;
        unpk2(r2a, h0, h1); u64 ra = pk2(rsqrt_ap(h0), rsqrt_ap(h1));
        unpk2(r2b, h0, h1); u64 rb = pk2(rsqrt_ap(h0), rsqrt_ap(h1));
        unpk2(r2c, h0, h1); u64 rc = pk2(rsqrt_ap(h0), rsqrt_ap(h1));
        u64 la = mulpk(r2a, ra), lb = mulpk(r2b, rb), lc = mulpk(r2c, rc);
        u64 dab = fmapk(az, bz, fmapk(ay, by, mulpk(ax, bx)));
        u64 dbc = fmapk(bz, cz, fmapk(by, cy, mulpk(bx, cx)));
        u64 dca = fmapk(cz, az, fmapk(cy, ay, mulpk(cx, ax)));
        u64 denom = fmapk(fmapk(la, lb, dab), lc, fmapk(dbc, la, mulpk(dca, lb)));
        // hybrid atan2: scalar quadrant prep, packed polynomial, scalar fixups
        float y0, y1, x0, x1;
        unpk2(det, y0, y1); unpk2(denom, x0, x1);
        float aX0 = fabsf(x0), aY0 = fabsf(y0);
        float aX1 = fabsf(x1), aY1 = fabsf(y1);
        float mx0 = fmaxf(aX0, aY0), mn0 = fminf(aX0, aY0);
        float mx1 = fmaxf(aX1, aY1), mn1 = fminf(aX1, aY1);
        float t0 = mn0 * rcp_ap(fmaxf(mx0, 1e-37f));
        float t1 = mn1 * rcp_ap(fmaxf(mx1, 1e-37f));
        u64 tp = pk2(t0, t1);
        u64 sp = mulpk(tp, tp);
        u64 pp = PC0;
        pp = fmapk(pp, sp, PC1);
        pp = fmapk(pp, sp, PC2);
        pp = fmapk(pp, sp, PC3);
        pp = fmapk(pp, sp, PC4);
        pp = fmapk(pp, sp, PC5);
        u64 rp = mulpk(pp, tp);
        float r0, r1; unpk2(rp, r0, r1);
        r0 = (aY0 > aX0) ? (1.5707963267948966f - r0) : r0;
        r1 = (aY1 > aX1) ? (1.5707963267948966f - r1) : r1;
        r0 = (x0 < 0.f) ? (3.1415926535897932f - r0) : r0;
        r1 = (x1 < 0.f) ? (3.1415926535897932f - r1) : r1;
        acc0 += copysignf(r0, y0);
        acc1 += copysignf(r1, y1);
    }
    size_t obase = ((size_t)(dir * BATCH + b) * FCMAX + fc) * NMAX;
    g_omega[obase + i0] = acc0;
    if (i1 < N) g_omega[obase + i1] = acc1;
}

// --------------------------- kernel C: reduce chunks -> mask, init rmin ----
__global__ void mask_kernel(int N, int FCH) {
    int i   = blockIdx.x * blockDim.x + threadIdx.x;
    int b   = blockIdx.y;
    int dir = blockIdx.z;
    if (i >= N) return;
    float s = 0.f;
    for (int fc = 0; fc < FCH; ++fc)
        s += g_omega[((size_t)(dir * BATCH + b) * FCMAX + fc) * NMAX + i];
    // w = (2 * sum_atan2) / (4*pi) = sum / (2*pi)
    float w = s * 0.15915494309189535f;
    int slot = (dir * BATCH + b) * NMAX + i;
    g_mask[slot]   = (w >= 0.99f) ? 1 : 0;
    g_rminsq[slot] = 0x7F7FFFFF;   // FLT_MAX bits
}

// --------------------------- kernel E: pairwise min (packed) ---------------
// 8 queries/thread as 4 packed pairs; targets staged pre-broadcast in smem.
// tracks v = o2 - 2*dot; q2 added + clamped at the end (monotone under min).
__global__ void __launch_bounds__(PT2) pairmin_kernel(const float* __restrict__ v1,
                               const float* __restrict__ v2,
                               int N) {
    int dir = blockIdx.z / OCH;
    int oc  = blockIdx.z % OCH;
    int b   = blockIdx.y;
    int tid = threadIdx.x;
    int ibase = blockIdx.x * (PT2 * QPK * 2) + tid;

    const float* Q = (dir == 0) ? v1 : v2;
    const float* O = (dir == 0) ? v2 : v1;

    __shared__ ulonglong2 s_pk[PTILE][2];   // [0]={(ox,ox),(oy,oy)} [1]={(oz,oz),(o2,o2)}

    u64 m2x[QPK], m2y[QPK], m2z[QPK];
    float q2[2 * QPK], m[2 * QPK];
    bool  vld[2 * QPK];
    #pragma unroll
    for (int k = 0; k < QPK; ++k) {
        int ia = ibase + (2 * k) * PT2;
        int ib = ibase + (2 * k + 1) * PT2;
        vld[2 * k]     = (ia < N);
        vld[2 * k + 1] = (ib < N);
        int la = min(ia, N - 1), lbi = min(ib, N - 1);
        const float* qa = Q + ((size_t)b * N + la) * 3;
        const float* qb = Q + ((size_t)b * N + lbi) * 3;
        float ax_ = qa[0], ay_ = qa[1], az_ = qa[2];
        float bx_ = qb[0], by_ = qb[1], bz_ = qb[2];
        m2x[k] = pk2(-2.f * ax_, -2.f * bx_);
        m2y[k] = pk2(-2.f * ay_, -2.f * by_);
        m2z[k] = pk2(-2.f * az_, -2.f * bz_);
        q2[2 * k]     = ax_ * ax_ + ay_ * ay_ + az_ * az_;
        q2[2 * k + 1] = bx_ * bx_ + by_ * by_ + bz_ * bz_;
        m[2 * k] = CUDART_INF_F; m[2 * k + 1] = CUDART_INF_F;
    }

    int per = (N + OCH - 1) / OCH;
    int j0 = oc * per;
    int j1 = min(N, j0 + per);

    for (int t0 = j0; t0 < j1; t0 += PTILE) {
        int cnt = min(PTILE, j1 - t0);
        __syncthreads();
        if (tid < cnt) {
            const float* o = O + ((size_t)b * N + t0 + tid) * 3;
            float ox = o[0], oy = o[1], oz = o[2];
            float ow = ox * ox + oy * oy + oz * oz;
            s_pk[tid][0] = make_ulonglong2(bc2(ox), bc2(oy));
            s_pk[tid][1] = make_ulonglong2(bc2(oz), bc2(ow));
        }
        __syncthreads();
        for (int j = 0; j < cnt; ++j) {
            ulonglong2 u0 = s_pk[j][0];
            ulonglong2 u1 = s_pk[j][1];
            #pragma unroll
            for (int k = 0; k < QPK; ++k) {
                u64 v = fmapk(m2x[k], u0.x,
                        fmapk(m2y[k], u0.y,
                        fmapk(m2z[k], u1.x, u1.y)));
                float v0, v1; unpk2(v, v0, v1);
                m[2 * k]     = fminf(m[2 * k],     v0);
                m[2 * k + 1] = fminf(m[2 * k + 1], v1);
            }
        }
    }
    #pragma unroll
    for (int p = 0; p < 2 * QPK; ++p) {
        if (vld[p]) {
            float d2 = fmaxf(m[p] + q2[p], 0.f);   // matches ref clamp semantics
            int i = ibase + p * PT2;
            atomicMin(&g_rminsq[(dir * BATCH + b) * NMAX + i], __float_as_int(d2));
        }
    }
}

// --------------------------- kernel F: masked stats + output ---------------
__global__ void stats_kernel(float* __restrict__ out, int N) {
    int b   = blockIdx.x;
    int dir = blockIdx.y;
    int t   = threadIdx.x;

    __shared__ float smax[256], ssum[256], smin[256];
    __shared__ int   scnt[256];

    float mx = -CUDART_INF_F, sum = 0.f, mnsq = CUDART_INF_F;
    int cnt = 0;
    int base = (dir * BATCH + b) * NMAX;
    for (int i = t; i < N; i += 256) {
        float rsq = __int_as_float(g_rminsq[base + i]);
        float r = sqrtf(rsq);
        if (g_mask[base + i]) { mx = fmaxf(mx, r); sum += r; cnt++; }
        mnsq = fminf(mnsq, rsq);
    }
    smax[t] = mx; ssum[t] = sum; smin[t] = mnsq; scnt[t] = cnt;
    __syncthreads();
    for (int s = 128; s > 0; s >>= 1) {
        if (t < s) {
            smax[t] = fmaxf(smax[t], smax[t + s]);
            ssum[t] += ssum[t + s];
            smin[t] = fminf(smin[t], smin[t + s]);
            scnt[t] += scnt[t + s];
        }
        __syncthreads();
    }
    if (t == 0) {
        int   c   = scnt[0];
        float mxv = (c > 0) ? smax[0] : 0.f;
        float mnv = (c > 0) ? ssum[0] / (float)c : 0.f;
        out[(1 + 2 * dir) * BATCH + b] = mxv;   // max_12 / max_21
        out[(2 + 2 * dir) * BATCH + b] = mnv;   // mean_12 / mean_21
        if (dir == 0) out[b] = sqrtf(smin[0]);  // min_dist
    }
}

// ---------------------------------------------------------------------------
extern "C" void kernel_launch(void* const* d_in, const int* in_sizes, int n_in,
                              void* d_out, int out_size) {
    const float* v1    = (const float*)d_in[0];
    const float* v2    = (const float*)d_in[1];
    const int*   faces = (const int*)d_in[2];
    float* out = (float*)d_out;

    int N  = in_sizes[0] / (BATCH * 3);
    int NF = in_sizes[2] / 3;
    int FCH = (NF + FTILE - 1) / FTILE;

    // A: gather triangle soups
    {
        int total = 2 * BATCH * NF * 3;
        build_tris_kernel<<<(total + 255) / 256, 256>>>(v1, v2, faces, N, NF);
    }
    // B: winding partial sums (2 points/thread, 256 points/block)
    {
        dim3 grid((N + 255) / 256, BATCH, 2 * FCH);
        winding_kernel<<<grid, 128>>>(v1, v2, N, NF, FCH);
    }
    // C: masks + rmin init
    {
        dim3 grid((N + 255) / 256, BATCH, 2);
        mask_kernel<<<grid, 256>>>(N, FCH);
    }
    // E: pairwise mins (8 queries/thread packed)
    {
        int span = PT2 * QPK * 2;
        dim3 grid((N + span - 1) / span, BATCH, 2 * OCH);
        pairmin_kernel<<<grid, PT2>>>(v1, v2, N);
    }
    // F: stats
    {
        dim3 grid(BATCH, 2);
        stats_kernel<<<grid, 256>>>(out, N);
    }
}